// round 3
// baseline (speedup 1.0000x reference)
#include <cuda_runtime.h>
#include <mma.h>

using namespace nvcuda;

// ---------------- problem constants ----------------
constexpr int B_  = 8;
constexpr int M_  = 8;
constexpr int D_  = 512;
constexpr int DH_ = 64;
constexpr int O_  = 64;
constexpr int SS_ = 72;    // M + O

constexpr int NTT = B_ * 512 * M_;  // 32768 temporal rows
constexpr int NSS = B_ * SS_;       // 576 ss rows

constexpr long long SZ_TOUT = (long long)B_ * 513 * M_ * D_;
constexpr long long SZ_OOUT = (long long)B_ * O_ * D_;
constexpr long long SZ_TATT = (long long)B_ * 8 * 512 * M_ * SS_;
constexpr long long OFF_OOUT = SZ_TOUT;
constexpr long long OFF_TATT = OFF_OOUT + SZ_OOUT;
constexpr long long OFF_OATT = OFF_TATT + SZ_TATT;

// ---------------- scratch ----------------
__device__ float g_tt[3][(size_t)NTT * D_];   // Qtt, Ktt, Vtt (no bias)
__device__ float g_ss[3][(size_t)NSS * D_];   // Qss, Kss, Vss (no bias)

__device__ __forceinline__ float to_tf32(float x) {
    asm("cvt.rna.tf32.f32 %0, %0;" : "+f"(x));
    return x;
}

// ============================================================================
// Projection GEMM v3: double-buffered smem, 1 sync per k-iter.
// BM=256 BN=128 BK=32, 512 threads / 16 warps (4x4), warp = 64x32.
// ============================================================================
constexpr int P_BM = 256, P_BN = 128, P_BK = 32, P_LD = P_BK + 4;
constexpr int P_BUF = (P_BM + P_BN) * P_LD;            // floats per buffer
constexpr int SMEM_PROJ = 2 * P_BUF * 4;               // 110592 bytes

template<int MODE>
__global__ __launch_bounds__(512) void proj_gemm(
    const float* __restrict__ Xt, const float* __restrict__ Xo,
    const float* __restrict__ Wq, const float* __restrict__ Wk,
    const float* __restrict__ Wv)
{
    extern __shared__ float sm[];

    const int tid  = threadIdx.x;
    const int warp = tid >> 5;
    const int wr   = warp >> 2;
    const int wc   = warp & 3;
    const int tm   = blockIdx.x;
    const int tn   = blockIdx.y;
    const int mat  = blockIdx.z;

    const float* W   = (mat == 0) ? Wq : ((mat == 1) ? Wk : Wv);
    float*       Out = (MODE == 0) ? g_tt[mat] : g_ss[mat];
    const int  Mrows = (MODE == 0) ? NTT : NSS;

    // per-thread staging coordinates
    const int ar = tid >> 3;              // A rows tid-based: handles r, r+64, r+128, r+192
    const int ac = (tid & 7) * 4;

    wmma::fragment<wmma::accumulator, 16, 16, 8, float> acc[4][2];
#pragma unroll
    for (int i = 0; i < 4; i++)
#pragma unroll
        for (int j = 0; j < 2; j++) wmma::fill_fragment(acc[i][j], 0.0f);

    float4 ra[4], rb[2];

    auto ldg = [&](int k0) {
#pragma unroll
        for (int i = 0; i < 4; i++) {
            int r  = ar + i * 64;
            int gr = tm * P_BM + r;
            float4 v = make_float4(0.f, 0.f, 0.f, 0.f);
            if (MODE == 0) {
                const float* src = Xt + (size_t)(gr + ((gr >> 12) << 3) + 8) * D_;
                v = *reinterpret_cast<const float4*>(src + k0 + ac);
            } else if (gr < NSS) {
                int bb = gr / SS_;
                int jj = gr - bb * SS_;
                const float* src = (jj < M_) ? (Xt + (size_t)(bb * 4104 + jj) * D_)
                                             : (Xo + (size_t)(bb * O_ + jj - M_) * D_);
                v = *reinterpret_cast<const float4*>(src + k0 + ac);
            }
            ra[i] = v;
        }
#pragma unroll
        for (int i = 0; i < 2; i++) {
            int r = ar + i * 64;
            rb[i] = *reinterpret_cast<const float4*>(W + (size_t)(tn * P_BN + r) * D_ + k0 + ac);
        }
    };

    auto sts = [&](int buf) {
        float* As = sm + buf * P_BUF;
        float* Bs = As + P_BM * P_LD;
#pragma unroll
        for (int i = 0; i < 4; i++) {
            float4 v = ra[i];
            v.x = to_tf32(v.x); v.y = to_tf32(v.y); v.z = to_tf32(v.z); v.w = to_tf32(v.w);
            *reinterpret_cast<float4*>(&As[(ar + i * 64) * P_LD + ac]) = v;
        }
#pragma unroll
        for (int i = 0; i < 2; i++) {
            float4 v = rb[i];
            v.x = to_tf32(v.x); v.y = to_tf32(v.y); v.z = to_tf32(v.z); v.w = to_tf32(v.w);
            *reinterpret_cast<float4*>(&Bs[(ar + i * 64) * P_LD + ac]) = v;
        }
    };

    ldg(0);
    sts(0);
    __syncthreads();

    for (int kt = 0; kt < D_ / P_BK; kt++) {
        if (kt + 1 < D_ / P_BK) ldg((kt + 1) * P_BK);

        const float* As = sm + (kt & 1) * P_BUF;
        const float* Bs = As + P_BM * P_LD;
#pragma unroll
        for (int kk = 0; kk < P_BK; kk += 8) {
            wmma::fragment<wmma::matrix_a, 16, 16, 8, wmma::precision::tf32, wmma::row_major> af[4];
            wmma::fragment<wmma::matrix_b, 16, 16, 8, wmma::precision::tf32, wmma::col_major> bf[2];
#pragma unroll
            for (int i = 0; i < 4; i++)
                wmma::load_matrix_sync(af[i], &As[(wr * 64 + i * 16) * P_LD + kk], P_LD);
#pragma unroll
            for (int j = 0; j < 2; j++)
                wmma::load_matrix_sync(bf[j], &Bs[(wc * 32 + j * 16) * P_LD + kk], P_LD);
#pragma unroll
            for (int i = 0; i < 4; i++)
#pragma unroll
                for (int j = 0; j < 2; j++)
                    wmma::mma_sync(acc[i][j], af[i], bf[j], acc[i][j]);
        }
        if (kt + 1 < D_ / P_BK) sts((kt + 1) & 1);
        __syncthreads();
    }

#pragma unroll
    for (int i = 0; i < 4; i++) {
        int row0 = tm * P_BM + wr * 64 + i * 16;
        if (row0 + 16 <= Mrows) {
#pragma unroll
            for (int j = 0; j < 2; j++)
                wmma::store_matrix_sync(Out + (size_t)row0 * D_ + tn * P_BN + wc * 32 + j * 16,
                                        acc[i][j], D_, wmma::mem_row_major);
        }
    }
}

// ============================================================================
// Temporal attention v3 — all GEMMs on tensor cores (tf32 WMMA).
// Block = (b, h, chunk of 64 l). 256 threads / 8 warps.
// Per iter (8 l's = 64 rows):
//   S(64x128) = Q(64x64) . [Kl;Kts]^T        (wmma; tt diag blocks are valid)
//   softmax -> P(64x128) with zeros off the diagonal tt blocks
//   Out(64x64) = P(64x128) . [Vl;Vts]        (wmma; accumulators -> gmem)
// ============================================================================
constexpr int ST  = 68;    // row stride (floats) for Q/K/V tiles
constexpr int SPD = 132;   // row stride for S/P (64x128 + pad)
constexpr int SMEM_ATT = (64 * ST + 2 * 128 * ST + 64 * SPD + 3 * 64) * 4;  // 121600 B

__global__ __launch_bounds__(256) void temporal_attn_kernel(
    const float* __restrict__ bq, const float* __restrict__ bk,
    const float* __restrict__ bv, float* __restrict__ out)
{
    extern __shared__ float sm[];
    float* Ql  = sm;                   // [64][ST]
    float* Kst = Ql  + 64 * ST;        // [128][ST]  rows 0..63 = Kl (per iter), 64..127 = Kts
    float* Vst = Kst + 128 * ST;       // [128][ST]  rows 0..63 = Vl, 64..127 = Vts
    float* SP  = Vst + 128 * ST;       // [64][SPD]  S then P (aliased)
    float* bqs = SP  + 64 * SPD;
    float* bks = bqs + 64;
    float* bvs = bks + 64;

    const int tid  = threadIdx.x;
    const int warp = tid >> 5;
    const int lane = tid & 31;
    const int b  = blockIdx.z, h = blockIdx.y;
    const int l0 = blockIdx.x * 64;
    const int cb = h * DH_;
    const int c4 = (tid & 15) * 4;

    if (tid < 64) {
        bqs[tid] = bq[cb + tid];
        bks[tid] = bk[cb + tid];
        bvs[tid] = bv[cb + tid];
    }
    __syncthreads();

    const float4 bq4 = *reinterpret_cast<const float4*>(&bqs[c4]);
    const float4 bk4 = *reinterpret_cast<const float4*>(&bks[c4]);
    const float4 bv4 = *reinterpret_cast<const float4*>(&bvs[c4]);

    // ---- stage Kts/Vts once into rows 64..127 (bias + tf32) ----
#pragma unroll
    for (int i = 0; i < 4; i++) {
        int idx = tid + i * 256;
        int o = idx >> 4;
        size_t srow = (size_t)(b * SS_ + 8 + o) * D_ + cb + c4;
        float4 kv = *reinterpret_cast<const float4*>(&g_ss[1][srow]);
        kv.x = to_tf32(kv.x + bk4.x); kv.y = to_tf32(kv.y + bk4.y);
        kv.z = to_tf32(kv.z + bk4.z); kv.w = to_tf32(kv.w + bk4.w);
        *reinterpret_cast<float4*>(&Kst[(64 + o) * ST + c4]) = kv;
        float4 vv = *reinterpret_cast<const float4*>(&g_ss[2][srow]);
        vv.x = to_tf32(vv.x + bv4.x); vv.y = to_tf32(vv.y + bv4.y);
        vv.z = to_tf32(vv.z + bv4.z); vv.w = to_tf32(vv.w + bv4.w);
        *reinterpret_cast<float4*>(&Vst[(64 + o) * ST + c4]) = vv;
    }
    __syncthreads();

    for (int li0 = 0; li0 < 64; li0 += 8) {
        const size_t rbase = (size_t)b * 4096 + (size_t)(l0 + li0) * 8;

        // ---- stage Ql / Kl / Vl (rows 0..63), bias + tf32 ----
#pragma unroll
        for (int i = 0; i < 4; i++) {
            int idx = tid + i * 256;
            int r = idx >> 4;
            size_t off = (rbase + r) * D_ + cb + c4;
            float4 q = *reinterpret_cast<const float4*>(&g_tt[0][off]);
            q.x = to_tf32(q.x + bq4.x); q.y = to_tf32(q.y + bq4.y);
            q.z = to_tf32(q.z + bq4.z); q.w = to_tf32(q.w + bq4.w);
            *reinterpret_cast<float4*>(&Ql[r * ST + c4]) = q;
            float4 k = *reinterpret_cast<const float4*>(&g_tt[1][off]);
            k.x = to_tf32(k.x + bk4.x); k.y = to_tf32(k.y + bk4.y);
            k.z = to_tf32(k.z + bk4.z); k.w = to_tf32(k.w + bk4.w);
            *reinterpret_cast<float4*>(&Kst[r * ST + c4]) = k;
            float4 v = *reinterpret_cast<const float4*>(&g_tt[2][off]);
            v.x = to_tf32(v.x + bv4.x); v.y = to_tf32(v.y + bv4.y);
            v.z = to_tf32(v.z + bv4.z); v.w = to_tf32(v.w + bv4.w);
            *reinterpret_cast<float4*>(&Vst[r * ST + c4]) = v;
        }
        __syncthreads();

        // ---- S = Q . Kst^T  (64x128), warp -> 1 row-tile x 4 col-tiles ----
        {
            const int rt = warp >> 1;
            const int ct0 = (warp & 1) * 4;
            wmma::fragment<wmma::accumulator, 16, 16, 8, float> sacc[4];
#pragma unroll
            for (int j = 0; j < 4; j++) wmma::fill_fragment(sacc[j], 0.0f);
#pragma unroll
            for (int ks = 0; ks < 8; ks++) {
                wmma::fragment<wmma::matrix_a, 16, 16, 8, wmma::precision::tf32, wmma::row_major> af;
                wmma::load_matrix_sync(af, &Ql[(rt * 16) * ST + ks * 8], ST);
#pragma unroll
                for (int j = 0; j < 4; j++) {
                    wmma::fragment<wmma::matrix_b, 16, 16, 8, wmma::precision::tf32, wmma::col_major> bf;
                    wmma::load_matrix_sync(bf, &Kst[((ct0 + j) * 16) * ST + ks * 8], ST);
                    wmma::mma_sync(sacc[j], af, bf, sacc[j]);
                }
            }
#pragma unroll
            for (int j = 0; j < 4; j++)
                wmma::store_matrix_sync(&SP[(rt * 16) * SPD + (ct0 + j) * 16], sacc[j],
                                        SPD, wmma::mem_row_major);
        }
        __syncthreads();

        // ---- softmax: warp handles rows 8w..8w+7; reads S, writes P + gmem ----
        for (int i = 0; i < 8; i++) {
            int r = warp * 8 + i;
            int li = r >> 3;
            float* Pr = &SP[r * SPD];
            float v0 = Pr[64 + lane] * 0.125f;
            float v1 = Pr[96 + lane] * 0.125f;
            float vs = (lane < 8) ? Pr[li * 8 + lane] * 0.125f : -3.4e38f;
            float mx = fmaxf(fmaxf(v0, v1), vs);
#pragma unroll
            for (int s = 16; s; s >>= 1) mx = fmaxf(mx, __shfl_xor_sync(0xffffffffu, mx, s));
            float e0 = __expf(v0 - mx), e1 = __expf(v1 - mx);
            float es = (lane < 8) ? __expf(vs - mx) : 0.f;
            float smv = e0 + e1 + es;
#pragma unroll
            for (int s = 16; s; s >>= 1) smv += __shfl_xor_sync(0xffffffffu, smv, s);
            float inv = 1.0f / smv;
            float p0 = e0 * inv, p1 = e1 * inv;
            size_t abase = OFF_TATT + ((size_t)(b * 8 + h) * 4096 + (size_t)(l0 + li0 + li) * 8 + (r & 7)) * 72;
            out[abase + 8 + lane]  = p0;
            out[abase + 40 + lane] = p1;
            float ps = es * inv;
            if (lane < 8) out[abase + lane] = ps;
            // build P row: zeros in cols 0..63 except the diagonal tt block
            Pr[lane] = 0.f;
            Pr[32 + lane] = 0.f;
            __syncwarp();
            Pr[64 + lane] = to_tf32(p0);
            Pr[96 + lane] = to_tf32(p1);
            if (lane < 8) Pr[li * 8 + lane] = to_tf32(ps);
        }
        __syncthreads();

        // ---- Out = P . Vst  (64x64), warp -> 1 row-tile x 2 col-tiles ----
        {
            const int rt = warp >> 1;
            const int ct0 = (warp & 1) * 2;
            wmma::fragment<wmma::accumulator, 16, 16, 8, float> oacc[2];
#pragma unroll
            for (int j = 0; j < 2; j++) wmma::fill_fragment(oacc[j], 0.0f);
#pragma unroll
            for (int ks = 0; ks < 16; ks++) {
                wmma::fragment<wmma::matrix_a, 16, 16, 8, wmma::precision::tf32, wmma::row_major> af;
                wmma::load_matrix_sync(af, &SP[(rt * 16) * SPD + ks * 8], SPD);
#pragma unroll
                for (int j = 0; j < 2; j++) {
                    wmma::fragment<wmma::matrix_b, 16, 16, 8, wmma::precision::tf32, wmma::row_major> bf;
                    wmma::load_matrix_sync(bf, &Vst[(ks * 8) * ST + (ct0 + j) * 16], ST);
                    wmma::mma_sync(oacc[j], af, bf, oacc[j]);
                }
            }
            const size_t g0 = (size_t)(b * 4104 + 8 + (l0 + li0) * 8 + rt * 16);
#pragma unroll
            for (int j = 0; j < 2; j++)
                wmma::store_matrix_sync(out + g0 * D_ + cb + (ct0 + j) * 16, oacc[j],
                                        D_, wmma::mem_row_major);
        }
        __syncthreads();
    }
}

// ============================================================================
// Others attention (unchanged).
// ============================================================================
__global__ void others_attn_kernel(const float* __restrict__ bq, const float* __restrict__ bk,
                                   const float* __restrict__ bv, float* __restrict__ out)
{
    __shared__ float Qc[24][65];
    __shared__ float KV[72][65];
    __shared__ float S[24][73];
    __shared__ float bq_s[64], bk_s[64], bv_s[64];

    const int tid = threadIdx.x;
    const int m0 = blockIdx.x * 24;
    const int h = blockIdx.y, b = blockIdx.z;
    const int cb = h * DH_;

    if (tid < 64) {
        bq_s[tid] = bq[cb + tid];
        bk_s[tid] = bk[cb + tid];
        bv_s[tid] = bv[cb + tid];
    }
    __syncthreads();

    for (int idx = tid; idx < 72 * 64; idx += 256) {
        int n = idx >> 6, d = idx & 63;
        KV[n][d] = g_ss[1][(size_t)(b * SS_ + n) * D_ + cb + d] + bk_s[d];
    }
    for (int idx = tid; idx < 24 * 64; idx += 256) {
        int i = idx >> 6, d = idx & 63;
        Qc[i][d] = g_ss[0][(size_t)(b * SS_ + m0 + i) * D_ + cb + d] + bq_s[d];
    }
    __syncthreads();

    for (int e = tid; e < 24 * 72; e += 256) {
        int i = e / 72, n = e - i * 72;
        float acc = 0.f;
#pragma unroll
        for (int d = 0; d < 64; d++) acc = fmaf(Qc[i][d], KV[n][d], acc);
        S[i][n] = acc * 0.125f;
    }
    __syncthreads();

    {
        int w = tid >> 5, lane = tid & 31;
        for (int i = w; i < 24; i += 8) {
            float v0 = S[i][lane];
            float v1 = S[i][lane + 32];
            float v2 = (lane < 8) ? S[i][lane + 64] : -3.4e38f;
            float mx = fmaxf(fmaxf(v0, v1), v2);
#pragma unroll
            for (int s = 16; s; s >>= 1) mx = fmaxf(mx, __shfl_xor_sync(0xffffffffu, mx, s));
            float e0 = __expf(v0 - mx), e1 = __expf(v1 - mx);
            float e2 = (lane < 8) ? __expf(v2 - mx) : 0.f;
            float smv = e0 + e1 + e2;
#pragma unroll
            for (int s = 16; s; s >>= 1) smv += __shfl_xor_sync(0xffffffffu, smv, s);
            float inv = 1.0f / smv;
            size_t abase = OFF_OATT + ((size_t)(b * 8 + h) * 72 + (m0 + i)) * 72;
            float p0 = e0 * inv, p1 = e1 * inv;
            S[i][lane] = p0;       out[abase + lane]      = p0;
            S[i][lane + 32] = p1;  out[abase + lane + 32] = p1;
            if (lane < 8) {
                float p2 = e2 * inv;
                S[i][lane + 64] = p2;
                out[abase + lane + 64] = p2;
            }
        }
    }
    __syncthreads();

    for (int idx = tid; idx < 72 * 64; idx += 256) {
        int n = idx >> 6, d = idx & 63;
        KV[n][d] = g_ss[2][(size_t)(b * SS_ + n) * D_ + cb + d] + bv_s[d];
    }
    __syncthreads();

    for (int e = tid; e < 24 * 64; e += 256) {
        int i = e >> 6, d = e & 63;
        float acc = 0.f;
#pragma unroll
        for (int n = 0; n < 72; n++) acc = fmaf(S[i][n], KV[n][d], acc);
        int ng = m0 + i;
        int p = h * 4608 + ng * 64 + d;
        int j = p >> 9;
        int c = p & 511;
        if (j < 8)
            out[(size_t)(b * 4104 + j) * D_ + c] = acc;
        else
            out[OFF_OOUT + (size_t)(b * 64 + (j - 8)) * D_ + c] = acc;
    }
}

// ============================================================================
extern "C" void kernel_launch(void* const* d_in, const int* in_sizes, int n_in,
                              void* d_out, int out_size)
{
    const float* Xt = (const float*)d_in[0];
    const float* Xo = (const float*)d_in[1];
    const float* Wq = (const float*)d_in[2];
    const float* bq = (const float*)d_in[3];
    const float* Wk = (const float*)d_in[4];
    const float* bk = (const float*)d_in[5];
    const float* Wv = (const float*)d_in[6];
    const float* bv = (const float*)d_in[7];
    float* out = (float*)d_out;

    cudaFuncSetAttribute((const void*)proj_gemm<0>, cudaFuncAttributeMaxDynamicSharedMemorySize, SMEM_PROJ);
    cudaFuncSetAttribute((const void*)proj_gemm<1>, cudaFuncAttributeMaxDynamicSharedMemorySize, SMEM_PROJ);
    cudaFuncSetAttribute((const void*)temporal_attn_kernel, cudaFuncAttributeMaxDynamicSharedMemorySize, SMEM_ATT);

    proj_gemm<0><<<dim3(NTT / P_BM, D_ / P_BN, 3), 512, SMEM_PROJ>>>(Xt, Xo, Wq, Wk, Wv);
    proj_gemm<1><<<dim3((NSS + P_BM - 1) / P_BM, D_ / P_BN, 3), 512, SMEM_PROJ>>>(Xt, Xo, Wq, Wk, Wv);
    temporal_attn_kernel<<<dim3(8, 8, 8), 256, SMEM_ATT>>>(bq, bk, bv, out);
    others_attn_kernel<<<dim3(3, 8, 8), 256>>>(bq, bk, bv, out);
}

// round 5
// speedup vs baseline: 2.7928x; 2.7928x over previous
#include <cuda_runtime.h>
#include <cuda_fp16.h>
#include <mma.h>

using namespace nvcuda;

// ---------------- problem constants ----------------
constexpr int B_  = 8;
constexpr int M_  = 8;
constexpr int D_  = 512;
constexpr int DH_ = 64;
constexpr int O_  = 64;
constexpr int SS_ = 72;    // M + O

constexpr int NTT = B_ * 512 * M_;  // 32768 temporal rows
constexpr int NSS = B_ * SS_;       // 576 ss rows

constexpr long long SZ_TOUT = (long long)B_ * 513 * M_ * D_;
constexpr long long SZ_OOUT = (long long)B_ * O_ * D_;
constexpr long long SZ_TATT = (long long)B_ * 8 * 512 * M_ * SS_;
constexpr long long OFF_OOUT = SZ_TOUT;
constexpr long long OFF_TATT = OFF_OOUT + SZ_OOUT;
constexpr long long OFF_OATT = OFF_TATT + SZ_TATT;

// ---------------- scratch ----------------
__device__ float g_tt[3][(size_t)NTT * D_];   // Qtt, Ktt, Vtt (no bias)
__device__ float g_ss[3][(size_t)NSS * D_];   // Qss, Kss, Vss (no bias)

// ============================================================================
// Projection GEMM v5: fp16 WMMA (m16n16k16), fp32 accumulate.
// BM=256 BN=128 BK=32, 512 threads / 16 warps (4x4), warp = 64x32.
// Double-buffered smem. C[r,n] = sum_d X[r,d]*W[n,d]; bias deferred.
// ============================================================================
constexpr int P_BM = 256, P_BN = 128, P_BK = 32, P_LD = P_BK + 8;  // halves
constexpr int P_BUF = (P_BM + P_BN) * P_LD;                        // halves per buffer
constexpr int SMEM_PROJ = 2 * P_BUF * 2;                           // 61440 bytes

template<int MODE>
__global__ __launch_bounds__(512) void proj_gemm(
    const float* __restrict__ Xt, const float* __restrict__ Xo,
    const float* __restrict__ Wq, const float* __restrict__ Wk,
    const float* __restrict__ Wv)
{
    extern __shared__ __half smh[];

    const int tid  = threadIdx.x;
    const int warp = tid >> 5;
    const int wr   = warp >> 2;
    const int wc   = warp & 3;
    const int tm   = blockIdx.x;
    const int tn   = blockIdx.y;
    const int mat  = blockIdx.z;

    const float* W   = (mat == 0) ? Wq : ((mat == 1) ? Wk : Wv);
    float*       Out = (MODE == 0) ? g_tt[mat] : g_ss[mat];
    const int  Mrows = (MODE == 0) ? NTT : NSS;

    const int ar = tid >> 3;          // base row; strided by 64
    const int ac = (tid & 7) * 4;     // col (halves/floats)

    wmma::fragment<wmma::accumulator, 16, 16, 16, float> acc[4][2];
#pragma unroll
    for (int i = 0; i < 4; i++)
#pragma unroll
        for (int j = 0; j < 2; j++) wmma::fill_fragment(acc[i][j], 0.0f);

    float4 ra[4], rb[2];

    auto ldg = [&](int k0) {
#pragma unroll
        for (int i = 0; i < 4; i++) {
            int r  = ar + i * 64;
            int gr = tm * P_BM + r;
            float4 v = make_float4(0.f, 0.f, 0.f, 0.f);
            if (MODE == 0) {
                const float* src = Xt + (size_t)(gr + ((gr >> 12) << 3) + 8) * D_;
                v = *reinterpret_cast<const float4*>(src + k0 + ac);
            } else if (gr < NSS) {
                int bb = gr / SS_;
                int jj = gr - bb * SS_;
                const float* src = (jj < M_) ? (Xt + (size_t)(bb * 4104 + jj) * D_)
                                             : (Xo + (size_t)(bb * O_ + jj - M_) * D_);
                v = *reinterpret_cast<const float4*>(src + k0 + ac);
            }
            ra[i] = v;
        }
#pragma unroll
        for (int i = 0; i < 2; i++) {
            int r = ar + i * 64;
            rb[i] = *reinterpret_cast<const float4*>(W + (size_t)(tn * P_BN + r) * D_ + k0 + ac);
        }
    };

    auto sts = [&](int buf) {
        __half* As = smh + buf * P_BUF;
        __half* Bs = As + P_BM * P_LD;
#pragma unroll
        for (int i = 0; i < 4; i++) {
            __half2 h01 = __floats2half2_rn(ra[i].x, ra[i].y);
            __half2 h23 = __floats2half2_rn(ra[i].z, ra[i].w);
            *reinterpret_cast<__half2*>(&As[(ar + i * 64) * P_LD + ac])     = h01;
            *reinterpret_cast<__half2*>(&As[(ar + i * 64) * P_LD + ac + 2]) = h23;
        }
#pragma unroll
        for (int i = 0; i < 2; i++) {
            __half2 h01 = __floats2half2_rn(rb[i].x, rb[i].y);
            __half2 h23 = __floats2half2_rn(rb[i].z, rb[i].w);
            *reinterpret_cast<__half2*>(&Bs[(ar + i * 64) * P_LD + ac])     = h01;
            *reinterpret_cast<__half2*>(&Bs[(ar + i * 64) * P_LD + ac + 2]) = h23;
        }
    };

    ldg(0);
    sts(0);
    __syncthreads();

    for (int kt = 0; kt < D_ / P_BK; kt++) {
        if (kt + 1 < D_ / P_BK) ldg((kt + 1) * P_BK);

        const __half* As = smh + (kt & 1) * P_BUF;
        const __half* Bs = As + P_BM * P_LD;
#pragma unroll
        for (int kk = 0; kk < P_BK; kk += 16) {
            wmma::fragment<wmma::matrix_a, 16, 16, 16, __half, wmma::row_major> af[4];
            wmma::fragment<wmma::matrix_b, 16, 16, 16, __half, wmma::col_major> bf[2];
#pragma unroll
            for (int i = 0; i < 4; i++)
                wmma::load_matrix_sync(af[i], &As[(wr * 64 + i * 16) * P_LD + kk], P_LD);
#pragma unroll
            for (int j = 0; j < 2; j++)
                wmma::load_matrix_sync(bf[j], &Bs[(wc * 32 + j * 16) * P_LD + kk], P_LD);
#pragma unroll
            for (int i = 0; i < 4; i++)
#pragma unroll
                for (int j = 0; j < 2; j++)
                    wmma::mma_sync(acc[i][j], af[i], bf[j], acc[i][j]);
        }
        if (kt + 1 < D_ / P_BK) sts((kt + 1) & 1);
        __syncthreads();
    }

#pragma unroll
    for (int i = 0; i < 4; i++) {
        int row0 = tm * P_BM + wr * 64 + i * 16;
        if (row0 + 16 <= Mrows) {
#pragma unroll
            for (int j = 0; j < 2; j++)
                wmma::store_matrix_sync(Out + (size_t)row0 * D_ + tn * P_BN + wc * 32 + j * 16,
                                        acc[i][j], D_, wmma::mem_row_major);
        }
    }
}

// ============================================================================
// Temporal attention v5 — fp16 WMMA for S and PV, fp32 softmax.
// Block = (b, h, chunk of 64 l). 256 threads / 8 warps.
// ============================================================================
constexpr int ST  = 72;    // halves stride for Q/K/V tiles (64 + 8)
constexpr int SPD = 132;   // floats stride for S (64x128 + pad)
constexpr int PHD = 136;   // halves stride for P (64x128 + pad)
constexpr int SMEM_ATT =
    64 * ST * 2              // Ql
  + 128 * ST * 2             // Kst
  + 128 * ST * 2             // Vst
  + 64 * SPD * 4             // S (float)
  + 64 * PHD * 2             // P (half)
  + 3 * 64 * 4;              // biases

__global__ __launch_bounds__(256) void temporal_attn_kernel(
    const float* __restrict__ bq, const float* __restrict__ bk,
    const float* __restrict__ bv, float* __restrict__ out)
{
    extern __shared__ char smc[];
    __half* Ql  = reinterpret_cast<__half*>(smc);
    __half* Kst = Ql  + 64 * ST;
    __half* Vst = Kst + 128 * ST;
    float*  SP  = reinterpret_cast<float*>(Vst + 128 * ST);
    __half* Ph  = reinterpret_cast<__half*>(SP + 64 * SPD);
    float*  bqs = reinterpret_cast<float*>(Ph + 64 * PHD);
    float*  bks = bqs + 64;
    float*  bvs = bks + 64;

    const int tid  = threadIdx.x;
    const int warp = tid >> 5;
    const int lane = tid & 31;
    const int b  = blockIdx.z, h = blockIdx.y;
    const int l0 = blockIdx.x * 64;
    const int cb = h * DH_;
    const int c4 = (tid & 15) * 4;

    if (tid < 64) {
        bqs[tid] = bq[cb + tid];
        bks[tid] = bk[cb + tid];
        bvs[tid] = bv[cb + tid];
    }
    __syncthreads();

    const float4 bq4 = *reinterpret_cast<const float4*>(&bqs[c4]);
    const float4 bk4 = *reinterpret_cast<const float4*>(&bks[c4]);
    const float4 bv4 = *reinterpret_cast<const float4*>(&bvs[c4]);

    auto st_h4 = [](__half* dst, float x, float y, float z, float w) {
        __half2 h01 = __floats2half2_rn(x, y);
        __half2 h23 = __floats2half2_rn(z, w);
        *reinterpret_cast<__half2*>(dst)     = h01;
        *reinterpret_cast<__half2*>(dst + 2) = h23;
    };

    // ---- stage Kts/Vts once into rows 64..127 (bias added) ----
#pragma unroll
    for (int i = 0; i < 4; i++) {
        int idx = tid + i * 256;
        int o = idx >> 4;
        size_t srow = (size_t)(b * SS_ + 8 + o) * D_ + cb + c4;
        float4 kv = *reinterpret_cast<const float4*>(&g_ss[1][srow]);
        st_h4(&Kst[(64 + o) * ST + c4], kv.x + bk4.x, kv.y + bk4.y, kv.z + bk4.z, kv.w + bk4.w);
        float4 vv = *reinterpret_cast<const float4*>(&g_ss[2][srow]);
        st_h4(&Vst[(64 + o) * ST + c4], vv.x + bv4.x, vv.y + bv4.y, vv.z + bv4.z, vv.w + bv4.w);
    }
    __syncthreads();

    for (int li0 = 0; li0 < 64; li0 += 8) {
        const size_t rbase = (size_t)b * 4096 + (size_t)(l0 + li0) * 8;

        // ---- stage Ql / Kl / Vl (rows 0..63) ----
#pragma unroll
        for (int i = 0; i < 4; i++) {
            int idx = tid + i * 256;
            int r = idx >> 4;
            size_t off = (rbase + r) * D_ + cb + c4;
            float4 q = *reinterpret_cast<const float4*>(&g_tt[0][off]);
            st_h4(&Ql[r * ST + c4], q.x + bq4.x, q.y + bq4.y, q.z + bq4.z, q.w + bq4.w);
            float4 k = *reinterpret_cast<const float4*>(&g_tt[1][off]);
            st_h4(&Kst[r * ST + c4], k.x + bk4.x, k.y + bk4.y, k.z + bk4.z, k.w + bk4.w);
            float4 v = *reinterpret_cast<const float4*>(&g_tt[2][off]);
            st_h4(&Vst[r * ST + c4], v.x + bv4.x, v.y + bv4.y, v.z + bv4.z, v.w + bv4.w);
        }
        __syncthreads();

        // ---- S = Q . Kst^T  (64x128) fp16 wmma; warp: 1 row-tile x 4 col-tiles ----
        {
            const int rt = warp >> 1;
            const int ct0 = (warp & 1) * 4;
            wmma::fragment<wmma::accumulator, 16, 16, 16, float> sacc[4];
#pragma unroll
            for (int j = 0; j < 4; j++) wmma::fill_fragment(sacc[j], 0.0f);
#pragma unroll
            for (int ks = 0; ks < 4; ks++) {
                wmma::fragment<wmma::matrix_a, 16, 16, 16, __half, wmma::row_major> af;
                wmma::load_matrix_sync(af, &Ql[(rt * 16) * ST + ks * 16], ST);
#pragma unroll
                for (int j = 0; j < 4; j++) {
                    wmma::fragment<wmma::matrix_b, 16, 16, 16, __half, wmma::col_major> bf;
                    wmma::load_matrix_sync(bf, &Kst[((ct0 + j) * 16) * ST + ks * 16], ST);
                    wmma::mma_sync(sacc[j], af, bf, sacc[j]);
                }
            }
#pragma unroll
            for (int j = 0; j < 4; j++)
                wmma::store_matrix_sync(&SP[(rt * 16) * SPD + (ct0 + j) * 16], sacc[j],
                                        SPD, wmma::mem_row_major);
        }
        __syncthreads();

        // ---- softmax: warp handles rows 8w..8w+7 ----
        for (int i = 0; i < 8; i++) {
            int r = warp * 8 + i;
            int li = r >> 3;
            float* Sr = &SP[r * SPD];
            __half* Pr = &Ph[r * PHD];
            float v0 = Sr[64 + lane] * 0.125f;
            float v1 = Sr[96 + lane] * 0.125f;
            float vs = (lane < 8) ? Sr[li * 8 + lane] * 0.125f : -3.4e38f;
            float mx = fmaxf(fmaxf(v0, v1), vs);
#pragma unroll
            for (int s = 16; s; s >>= 1) mx = fmaxf(mx, __shfl_xor_sync(0xffffffffu, mx, s));
            float e0 = __expf(v0 - mx), e1 = __expf(v1 - mx);
            float es = (lane < 8) ? __expf(vs - mx) : 0.f;
            float smv = e0 + e1 + es;
#pragma unroll
            for (int s = 16; s; s >>= 1) smv += __shfl_xor_sync(0xffffffffu, smv, s);
            float inv = 1.0f / smv;
            float p0 = e0 * inv, p1 = e1 * inv;
            size_t abase = OFF_TATT + ((size_t)(b * 8 + h) * 4096 + (size_t)(l0 + li0 + li) * 8 + (r & 7)) * 72;
            out[abase + 8 + lane]  = p0;
            out[abase + 40 + lane] = p1;
            float ps = es * inv;
            if (lane < 8) out[abase + lane] = ps;
            // P row (half): zeros in cols 0..63 except diagonal tt block
            Pr[lane]      = __float2half_rn(0.f);
            Pr[32 + lane] = __float2half_rn(0.f);
            __syncwarp();
            Pr[64 + lane] = __float2half_rn(p0);
            Pr[96 + lane] = __float2half_rn(p1);
            if (lane < 8) Pr[li * 8 + lane] = __float2half_rn(ps);
        }
        __syncthreads();

        // ---- Out = P . Vst  (64x64) fp16 wmma; warp: 1 row-tile x 2 col-tiles ----
        {
            const int rt = warp >> 1;
            const int ct0 = (warp & 1) * 2;
            wmma::fragment<wmma::accumulator, 16, 16, 16, float> oacc[2];
#pragma unroll
            for (int j = 0; j < 2; j++) wmma::fill_fragment(oacc[j], 0.0f);
#pragma unroll
            for (int ks = 0; ks < 8; ks++) {
                wmma::fragment<wmma::matrix_a, 16, 16, 16, __half, wmma::row_major> af;
                wmma::load_matrix_sync(af, &Ph[(rt * 16) * PHD + ks * 16], PHD);
#pragma unroll
                for (int j = 0; j < 2; j++) {
                    wmma::fragment<wmma::matrix_b, 16, 16, 16, __half, wmma::row_major> bf;
                    wmma::load_matrix_sync(bf, &Vst[(ks * 16) * ST + (ct0 + j) * 16], ST);
                    wmma::mma_sync(oacc[j], af, bf, oacc[j]);
                }
            }
            const size_t g0 = (size_t)(b * 4104 + 8 + (l0 + li0) * 8 + rt * 16);
#pragma unroll
            for (int j = 0; j < 2; j++)
                wmma::store_matrix_sync(out + g0 * D_ + cb + (ct0 + j) * 16, oacc[j],
                                        D_, wmma::mem_row_major);
        }
        __syncthreads();
    }
}

// ============================================================================
// Others attention (unchanged).
// ============================================================================
__global__ void others_attn_kernel(const float* __restrict__ bq, const float* __restrict__ bk,
                                   const float* __restrict__ bv, float* __restrict__ out)
{
    __shared__ float Qc[24][65];
    __shared__ float KV[72][65];
    __shared__ float S[24][73];
    __shared__ float bq_s[64], bk_s[64], bv_s[64];

    const int tid = threadIdx.x;
    const int m0 = blockIdx.x * 24;
    const int h = blockIdx.y, b = blockIdx.z;
    const int cb = h * DH_;

    if (tid < 64) {
        bq_s[tid] = bq[cb + tid];
        bk_s[tid] = bk[cb + tid];
        bv_s[tid] = bv[cb + tid];
    }
    __syncthreads();

    for (int idx = tid; idx < 72 * 64; idx += 256) {
        int n = idx >> 6, d = idx & 63;
        KV[n][d] = g_ss[1][(size_t)(b * SS_ + n) * D_ + cb + d] + bk_s[d];
    }
    for (int idx = tid; idx < 24 * 64; idx += 256) {
        int i = idx >> 6, d = idx & 63;
        Qc[i][d] = g_ss[0][(size_t)(b * SS_ + m0 + i) * D_ + cb + d] + bq_s[d];
    }
    __syncthreads();

    for (int e = tid; e < 24 * 72; e += 256) {
        int i = e / 72, n = e - i * 72;
        float acc = 0.f;
#pragma unroll
        for (int d = 0; d < 64; d++) acc = fmaf(Qc[i][d], KV[n][d], acc);
        S[i][n] = acc * 0.125f;
    }
    __syncthreads();

    {
        int w = tid >> 5, lane = tid & 31;
        for (int i = w; i < 24; i += 8) {
            float v0 = S[i][lane];
            float v1 = S[i][lane + 32];
            float v2 = (lane < 8) ? S[i][lane + 64] : -3.4e38f;
            float mx = fmaxf(fmaxf(v0, v1), v2);
#pragma unroll
            for (int s = 16; s; s >>= 1) mx = fmaxf(mx, __shfl_xor_sync(0xffffffffu, mx, s));
            float e0 = __expf(v0 - mx), e1 = __expf(v1 - mx);
            float e2 = (lane < 8) ? __expf(v2 - mx) : 0.f;
            float smv = e0 + e1 + e2;
#pragma unroll
            for (int s = 16; s; s >>= 1) smv += __shfl_xor_sync(0xffffffffu, smv, s);
            float inv = 1.0f / smv;
            size_t abase = OFF_OATT + ((size_t)(b * 8 + h) * 72 + (m0 + i)) * 72;
            float p0 = e0 * inv, p1 = e1 * inv;
            S[i][lane] = p0;       out[abase + lane]      = p0;
            S[i][lane + 32] = p1;  out[abase + lane + 32] = p1;
            if (lane < 8) {
                float p2 = e2 * inv;
                S[i][lane + 64] = p2;
                out[abase + lane + 64] = p2;
            }
        }
    }
    __syncthreads();

    for (int idx = tid; idx < 72 * 64; idx += 256) {
        int n = idx >> 6, d = idx & 63;
        KV[n][d] = g_ss[2][(size_t)(b * SS_ + n) * D_ + cb + d] + bv_s[d];
    }
    __syncthreads();

    for (int e = tid; e < 24 * 64; e += 256) {
        int i = e >> 6, d = e & 63;
        float acc = 0.f;
#pragma unroll
        for (int n = 0; n < 72; n++) acc = fmaf(S[i][n], KV[n][d], acc);
        int ng = m0 + i;
        int p = h * 4608 + ng * 64 + d;
        int j = p >> 9;
        int c = p & 511;
        if (j < 8)
            out[(size_t)(b * 4104 + j) * D_ + c] = acc;
        else
            out[OFF_OOUT + (size_t)(b * 64 + (j - 8)) * D_ + c] = acc;
    }
}

// ============================================================================
extern "C" void kernel_launch(void* const* d_in, const int* in_sizes, int n_in,
                              void* d_out, int out_size)
{
    const float* Xt = (const float*)d_in[0];
    const float* Xo = (const float*)d_in[1];
    const float* Wq = (const float*)d_in[2];
    const float* bq = (const float*)d_in[3];
    const float* Wk = (const float*)d_in[4];
    const float* bk = (const float*)d_in[5];
    const float* Wv = (const float*)d_in[6];
    const float* bv = (const float*)d_in[7];
    float* out = (float*)d_out;

    cudaFuncSetAttribute((const void*)proj_gemm<0>, cudaFuncAttributeMaxDynamicSharedMemorySize, SMEM_PROJ);
    cudaFuncSetAttribute((const void*)proj_gemm<1>, cudaFuncAttributeMaxDynamicSharedMemorySize, SMEM_PROJ);
    cudaFuncSetAttribute((const void*)temporal_attn_kernel, cudaFuncAttributeMaxDynamicSharedMemorySize, SMEM_ATT);

    proj_gemm<0><<<dim3(NTT / P_BM, D_ / P_BN, 3), 512, SMEM_PROJ>>>(Xt, Xo, Wq, Wk, Wv);
    proj_gemm<1><<<dim3((NSS + P_BM - 1) / P_BM, D_ / P_BN, 3), 512, SMEM_PROJ>>>(Xt, Xo, Wq, Wk, Wv);
    temporal_attn_kernel<<<dim3(8, 8, 8), 256, SMEM_ATT>>>(bq, bk, bv, out);
    others_attn_kernel<<<dim3(3, 8, 8), 256>>>(bq, bk, bv, out);
}